// round 4
// baseline (speedup 1.0000x reference)
#include <cuda_runtime.h>
#include <cuda_fp16.h>

#define NN   100000
#define EE   1000000
#define RR   4
#define GG   256
#define DHH  128
#define NCC  10
#define KK   (RR*DHH)   // 512
#define SB   98         // ceil(NN/1024)

#define AS_STRIDE 260   // uints per As row (256 + 4 pad) -> conflict-free frags
#define BS_STRIDE 12    // uints per Bs col (8 + 4 pad)
#define SMEM_BYTES ((128*AS_STRIDE + 2*128*BS_STRIDE) * 4)

// ---------------- scratch ----------------
__device__ __half    g_f16[(size_t)NN*DHH];   // fp16 features
__device__ __half    g_h0h[(size_t)NN*DHH];   // ping
__device__ __half    g_h1h[(size_t)NN*DHH];   // pong
__device__ unsigned  g_wt[3*DHH*256];         // per-layer W, transposed pair-packed half2
__device__ int       g_deg_out[RR*NN];
__device__ int       g_deg_in [RR*NN];
__device__ float     g_rno[RR*NN];
__device__ float     g_rni[RR*NN];
__device__ int       g_rowptr[RR*(NN+1)];
__device__ int       g_cursor[RR*NN];
__device__ unsigned  g_pcsr[(size_t)RR*EE];   // packed (src<<15)|(fp16 rno sans sign)
__device__ float     g_hg[GG*DHH];
__device__ int       g_gstart[GG+1];
__device__ int       g_bsum[RR*SB];

// ---------------- preprocessing ----------------
__global__ void zero_deg_k() {
    int i = blockIdx.x * blockDim.x + threadIdx.x;
    if (i < RR*NN) { g_deg_out[i] = 0; g_deg_in[i] = 0; }
}

__global__ void count_deg_k(const int* __restrict__ edges) {
    int i = blockIdx.x * blockDim.x + threadIdx.x;
    if (i >= RR*EE) return;
    int r = i / EE, e = i - r*EE;
    int src = edges[(size_t)r*2*EE + e];
    int dst = edges[(size_t)r*2*EE + EE + e];
    atomicAdd(&g_deg_out[r*NN + src], 1);
    atomicAdd(&g_deg_in [r*NN + dst], 1);
}

__global__ void rnorm_k() {
    int i = blockIdx.x * blockDim.x + threadIdx.x;
    if (i >= RR*NN) return;
    g_rno[i] = rsqrtf(fmaxf((float)g_deg_out[i], 1.0f));
    g_rni[i] = rsqrtf(fmaxf((float)g_deg_in [i], 1.0f));
}

__global__ void scan1_k() {
    __shared__ int sh[1024];
    int r = blockIdx.y, b = blockIdx.x, t = threadIdx.x;
    int i = b * 1024 + t;
    int v = (i < NN) ? g_deg_in[r*NN + i] : 0;
    sh[t] = v;
    __syncthreads();
    #pragma unroll
    for (int off = 1; off < 1024; off <<= 1) {
        int x = (t >= off) ? sh[t - off] : 0;
        __syncthreads();
        sh[t] += x;
        __syncthreads();
    }
    int excl = sh[t] - v;
    if (i < NN) g_rowptr[r*(NN+1) + i] = excl;
    if (t == 1023) g_bsum[r*SB + b] = sh[1023];
}

__global__ void scan2_k() {
    int r = threadIdx.x;
    if (r >= RR) return;
    int run = 0;
    for (int b = 0; b < SB; b++) {
        int v = g_bsum[r*SB + b];
        g_bsum[r*SB + b] = run;
        run += v;
    }
    g_rowptr[r*(NN+1) + NN] = run;
}

__global__ void scan3_k() {
    int i = blockIdx.x * blockDim.x + threadIdx.x;
    if (i >= RR*NN) return;
    int r = i / NN, n = i - r*NN;
    int off = g_bsum[r*SB + (n >> 10)];
    int v = g_rowptr[r*(NN+1) + n] + off;
    g_rowptr[r*(NN+1) + n] = v;
    g_cursor[r*NN + n] = v;
}

// fill CSR with packed (src, fp16 weight) entries
__global__ void fill_k(const int* __restrict__ edges) {
    int i = blockIdx.x * blockDim.x + threadIdx.x;
    if (i >= RR*EE) return;
    int r = i / EE, e = i - r*EE;
    int src = edges[(size_t)r*2*EE + e];
    int dst = edges[(size_t)r*2*EE + EE + e];
    float w = g_rno[r*NN + src];
    unsigned short hb = __half_as_ushort(__float2half_rn(w));  // sign bit = 0
    unsigned ent = ((unsigned)src << 15) | (unsigned)(hb & 0x7FFF);
    int pos = atomicAdd(&g_cursor[r*NN + dst], 1);
    g_pcsr[(size_t)r*EE + pos] = ent;
}

// ---------------- conversions ----------------
__global__ void conv_feat_k(const float* __restrict__ f) {
    int i = blockIdx.x * blockDim.x + threadIdx.x;
    if (i >= NN*DHH/2) return;
    float2 v = ((const float2*)f)[i];
    ((__half2*)g_f16)[i] = __floats2half2_rn(v.x, v.y);
}

// g_wt[l][col][pair] = half2(W_l[2p][col], W_l[2p+1][col])
__global__ void conv_w_k(const float* __restrict__ W0, const float* __restrict__ Wl) {
    int i = blockIdx.x * blockDim.x + threadIdx.x;
    if (i >= 3*DHH*256) return;
    int l = i / (DHH*256);
    int rem = i - l*DHH*256;
    int col = rem >> 8;
    int p = rem & 255;
    const float* src = (l == 0) ? W0 : Wl + (size_t)(l-1)*KK*DHH;
    __half2 hv = __floats2half2_rn(src[(size_t)(2*p)*DHH + col],
                                   src[(size_t)(2*p+1)*DHH + col]);
    g_wt[i] = *reinterpret_cast<unsigned*>(&hv);
}

// ---------------- fused aggregate + GEMM + bias + relu ----------------
__device__ __forceinline__ void mma_f16(float* c, const unsigned* a, const unsigned* b) {
    asm volatile(
        "mma.sync.aligned.m16n8k16.row.col.f32.f16.f16.f32 "
        "{%0,%1,%2,%3}, {%4,%5,%6,%7}, {%8,%9}, {%0,%1,%2,%3};"
        : "+f"(c[0]), "+f"(c[1]), "+f"(c[2]), "+f"(c[3])
        : "r"(a[0]), "r"(a[1]), "r"(a[2]), "r"(a[3]), "r"(b[0]), "r"(b[1]));
}

// block = 128 dst nodes, 512 threads (16 warps)
__global__ void __launch_bounds__(512) fused_layer_k(int sel, int layer,
                                                     const float* __restrict__ Bv,
                                                     int outsel) {
    extern __shared__ unsigned sm_u[];
    unsigned* As = sm_u;                         // [128][AS_STRIDE]
    unsigned* Bs = sm_u + 128*AS_STRIDE;         // [2][128][BS_STRIDE]

    const __half* hin = (sel == 0) ? g_f16 : (sel == 1 ? g_h0h : g_h1h);
    __half* O = (outsel == 0) ? g_h0h : g_h1h;
    const unsigned* Wt = g_wt + (size_t)layer*DHH*256;

    int tid = threadIdx.x;
    int rb = blockIdx.x * 128;
    int wid = tid >> 5, lane = tid & 31;

    // ---- preload Bs buffer 0 (independent of phase 1) ----
    {
        int f = tid * 2;
        int c = f >> 3, q = f & 7;
        uint2 w = *(const uint2*)(Wt + (size_t)c*256 + q);
        *(uint2*)&Bs[(size_t)c*BS_STRIDE + q] = w;
    }

    // ---- phase 1: gather 512 (r, n_local) tasks into As ----
    for (int tsk = wid; tsk < 512; tsk += 16) {
        int r = tsk >> 7, nl = tsk & 127;
        int n = rb + nl;
        float a0 = 0.f, a1 = 0.f, a2 = 0.f, a3 = 0.f;
        if (n < NN) {
            int e0 = g_rowptr[r*(NN+1) + n];
            int e1 = g_rowptr[r*(NN+1) + n + 1];
            const unsigned* pc = g_pcsr + (size_t)r*EE;
            for (int e = e0; e < e1; e++) {
                unsigned ent = __ldg(pc + e);
                int s = ent >> 15;
                float w = __half2float(__ushort_as_half((unsigned short)(ent & 0x7FFF)));
                uint2 v = __ldg((const uint2*)(hin + (size_t)s*DHH) + lane);
                float2 f01 = __half22float2(*reinterpret_cast<__half2*>(&v.x));
                float2 f23 = __half22float2(*reinterpret_cast<__half2*>(&v.y));
                a0 = fmaf(w, f01.x, a0);
                a1 = fmaf(w, f01.y, a1);
                a2 = fmaf(w, f23.x, a2);
                a3 = fmaf(w, f23.y, a3);
            }
            float ri = g_rni[r*NN + n];
            a0 *= ri; a1 *= ri; a2 *= ri; a3 *= ri;
        }
        __half2 p01 = __floats2half2_rn(a0, a1);
        __half2 p23 = __floats2half2_rn(a2, a3);
        uint2 o;
        o.x = *reinterpret_cast<unsigned*>(&p01);
        o.y = *reinterpret_cast<unsigned*>(&p23);
        *(uint2*)&As[(size_t)nl*AS_STRIDE + r*64 + lane*2] = o;
    }
    __syncthreads();

    // ---- phase 2: GEMM As[128x512] @ W[512x128] ----
    int wm = wid & 3, wn = wid >> 2;     // warp grid 4(m) x 4(n), warp tile 32x32
    int g = lane >> 2, t = lane & 3;

    float acc[2][4][4];
    #pragma unroll
    for (int mt = 0; mt < 2; mt++)
        #pragma unroll
        for (int nt = 0; nt < 4; nt++)
            #pragma unroll
            for (int j = 0; j < 4; j++) acc[mt][nt][j] = 0.f;

    int bc = (tid*2) >> 3, bq = (tid*2) & 7;   // Bs load indices
    uint2 breg;

    for (int kt = 0; kt < 32; kt++) {
        int cur = kt & 1;
        if (kt < 31)
            breg = *(const uint2*)(Wt + (size_t)bc*256 + (kt+1)*8 + bq);

        unsigned af[2][4], bf[4][2];
        #pragma unroll
        for (int mt = 0; mt < 2; mt++) {
            int r0 = wm*32 + mt*16 + g;
            const unsigned* Ar = As + (size_t)r0*AS_STRIDE + kt*8;
            af[mt][0] = Ar[t];
            af[mt][1] = Ar[8*AS_STRIDE + t];
            af[mt][2] = Ar[t + 4];
            af[mt][3] = Ar[8*AS_STRIDE + t + 4];
        }
        #pragma unroll
        for (int nt = 0; nt < 4; nt++) {
            int c0 = wn*32 + nt*8 + g;
            const unsigned* Bc = Bs + (size_t)cur*128*BS_STRIDE + (size_t)c0*BS_STRIDE;
            bf[nt][0] = Bc[t];
            bf[nt][1] = Bc[t + 4];
        }
        #pragma unroll
        for (int mt = 0; mt < 2; mt++)
            #pragma unroll
            for (int nt = 0; nt < 4; nt++)
                mma_f16(acc[mt][nt], af[mt], bf[nt]);

        if (kt < 31) {
            __syncthreads();
            *(uint2*)&Bs[(size_t)(cur^1)*128*BS_STRIDE + (size_t)bc*BS_STRIDE + bq] = breg;
            __syncthreads();
        }
    }

    // ---- bias (summed over relations) + relu + store ----
    float bias[4][2];
    #pragma unroll
    for (int nt = 0; nt < 4; nt++) {
        int c0 = wn*32 + nt*8 + 2*t;
        #pragma unroll
        for (int j = 0; j < 2; j++) {
            float s = 0.f;
            #pragma unroll
            for (int r = 0; r < RR; r++) s += Bv[r*DHH + c0 + j];
            bias[nt][j] = s;
        }
    }
    #pragma unroll
    for (int mt = 0; mt < 2; mt++) {
        int r0 = rb + wm*32 + mt*16 + g;
        #pragma unroll
        for (int nt = 0; nt < 4; nt++) {
            int c = wn*32 + nt*8 + 2*t;
            if (r0 < NN) {
                *(__half2*)(O + (size_t)r0*DHH + c) =
                    __floats2half2_rn(fmaxf(acc[mt][nt][0] + bias[nt][0], 0.f),
                                      fmaxf(acc[mt][nt][1] + bias[nt][1], 0.f));
            }
            if (r0 + 8 < NN) {
                *(__half2*)(O + (size_t)(r0+8)*DHH + c) =
                    __floats2half2_rn(fmaxf(acc[mt][nt][2] + bias[nt][0], 0.f),
                                      fmaxf(acc[mt][nt][3] + bias[nt][1], 0.f));
            }
        }
    }
}

// ---------------- pooling + classifier ----------------
__global__ void bounds_k(const int* __restrict__ gid) {
    int i = blockIdx.x * blockDim.x + threadIdx.x;
    if (i > NN) return;
    int cur  = (i < NN) ? gid[i] : GG;
    int prev = (i == 0) ? -1     : gid[i-1];
    for (int g = prev + 1; g <= cur; g++) g_gstart[g] = i;
}

__global__ void pool_k() {
    int g = blockIdx.x, j = threadIdx.x;
    int a = g_gstart[g], b = g_gstart[g+1];
    float s = 0.f;
    for (int n = a; n < b; n++) s += __half2float(g_h0h[(size_t)n*DHH + j]);
    float c = fmaxf((float)(b - a), 1.0f);
    g_hg[g*DHH + j] = s / c;
}

__global__ void cls_k(const float* __restrict__ Wc, const float* __restrict__ bc,
                      float* __restrict__ out) {
    int idx = blockIdx.x * blockDim.x + threadIdx.x;
    if (idx >= GG*NCC) return;
    int g = idx / NCC, c = idx - g*NCC;
    float s = bc[c];
    #pragma unroll 8
    for (int k = 0; k < DHH; k++)
        s = fmaf(g_hg[g*DHH + k], Wc[k*NCC + c], s);
    out[idx] = s;
}

// ---------------- launch ----------------
extern "C" void kernel_launch(void* const* d_in, const int* in_sizes, int n_in,
                              void* d_out, int out_size) {
    const float* features = (const float*)d_in[0];
    const int*   edges    = (const int*)  d_in[1];
    const int*   gids     = (const int*)  d_in[2];
    const float* W0       = (const float*)d_in[3];
    const float* b0       = (const float*)d_in[4];
    const float* Wl       = (const float*)d_in[5];
    const float* bl       = (const float*)d_in[6];
    const float* Wc       = (const float*)d_in[7];
    const float* bc       = (const float*)d_in[8];
    float* out = (float*)d_out;

    cudaFuncSetAttribute(fused_layer_k,
                         cudaFuncAttributeMaxDynamicSharedMemorySize, SMEM_BYTES);

    zero_deg_k <<<(RR*NN + 255)/256, 256>>>();
    count_deg_k<<<(RR*EE + 255)/256, 256>>>(edges);
    rnorm_k    <<<(RR*NN + 255)/256, 256>>>();
    scan1_k    <<<dim3(SB, RR), 1024>>>();
    scan2_k    <<<1, RR>>>();
    scan3_k    <<<(RR*NN + 255)/256, 256>>>();
    fill_k     <<<(RR*EE + 255)/256, 256>>>(edges);
    conv_feat_k<<<(NN*DHH/2 + 255)/256, 256>>>(features);
    conv_w_k   <<<(3*DHH*256 + 255)/256, 256>>>(W0, Wl);

    const int FUSED_BLOCKS = (NN + 127)/128;

    fused_layer_k<<<FUSED_BLOCKS, 512, SMEM_BYTES>>>(0, 0, b0, 0);            // feat -> h0
    fused_layer_k<<<FUSED_BLOCKS, 512, SMEM_BYTES>>>(1, 1, bl, 1);            // h0 -> h1
    fused_layer_k<<<FUSED_BLOCKS, 512, SMEM_BYTES>>>(2, 2, bl + RR*DHH, 0);   // h1 -> h0

    bounds_k<<<(NN + 256)/256, 256>>>(gids);
    pool_k  <<<GG, DHH>>>();
    cls_k   <<<(GG*NCC + 255)/256, 256>>>(Wc, bc, out);
}

// round 5
// speedup vs baseline: 1.3372x; 1.3372x over previous
#include <cuda_runtime.h>
#include <cuda_fp16.h>

#define NN   100000
#define EE   1000000
#define RR   4
#define GG   256
#define DHH  128
#define NCC  10
#define KK   (RR*DHH)   // 512
#define SB   98         // ceil(NN/1024)

// ---------------- scratch ----------------
__device__ __half    g_f16[(size_t)NN*DHH];   // fp16 features
__device__ __half    g_h0h[(size_t)NN*DHH];   // ping
__device__ __half    g_h1h[(size_t)NN*DHH];   // pong
__device__ __half    g_aggh[(size_t)NN*KK];   // concat aggregates (fp16)
__device__ unsigned  g_wt[3*DHH*256];         // per-layer W, transposed pair-packed half2
__device__ int       g_deg_out[RR*NN];
__device__ int       g_deg_in [RR*NN];
__device__ float     g_rno[RR*NN];
__device__ float     g_rni[RR*NN];
__device__ int       g_rowptr[RR*(NN+1)];
__device__ int       g_cursor[RR*NN];
__device__ unsigned  g_pcsr[(size_t)RR*EE];   // packed (src<<15)|(fp16 rno sans sign)
__device__ float     g_hg[GG*DHH];
__device__ int       g_gstart[GG+1];
__device__ int       g_bsum[RR*SB];

// ---------------- preprocessing ----------------
__global__ void zero_deg_k() {
    int i = blockIdx.x * blockDim.x + threadIdx.x;
    if (i < RR*NN) { g_deg_out[i] = 0; g_deg_in[i] = 0; }
}

__global__ void count_deg_k(const int* __restrict__ edges) {
    int i = blockIdx.x * blockDim.x + threadIdx.x;
    if (i >= RR*EE) return;
    int r = i / EE, e = i - r*EE;
    int src = edges[(size_t)r*2*EE + e];
    int dst = edges[(size_t)r*2*EE + EE + e];
    atomicAdd(&g_deg_out[r*NN + src], 1);
    atomicAdd(&g_deg_in [r*NN + dst], 1);
}

__global__ void rnorm_k() {
    int i = blockIdx.x * blockDim.x + threadIdx.x;
    if (i >= RR*NN) return;
    g_rno[i] = rsqrtf(fmaxf((float)g_deg_out[i], 1.0f));
    g_rni[i] = rsqrtf(fmaxf((float)g_deg_in [i], 1.0f));
}

__global__ void scan1_k() {
    __shared__ int sh[1024];
    int r = blockIdx.y, b = blockIdx.x, t = threadIdx.x;
    int i = b * 1024 + t;
    int v = (i < NN) ? g_deg_in[r*NN + i] : 0;
    sh[t] = v;
    __syncthreads();
    #pragma unroll
    for (int off = 1; off < 1024; off <<= 1) {
        int x = (t >= off) ? sh[t - off] : 0;
        __syncthreads();
        sh[t] += x;
        __syncthreads();
    }
    int excl = sh[t] - v;
    if (i < NN) g_rowptr[r*(NN+1) + i] = excl;
    if (t == 1023) g_bsum[r*SB + b] = sh[1023];
}

__global__ void scan2_k() {
    int r = threadIdx.x;
    if (r >= RR) return;
    int run = 0;
    for (int b = 0; b < SB; b++) {
        int v = g_bsum[r*SB + b];
        g_bsum[r*SB + b] = run;
        run += v;
    }
    g_rowptr[r*(NN+1) + NN] = run;
}

__global__ void scan3_k() {
    int i = blockIdx.x * blockDim.x + threadIdx.x;
    if (i >= RR*NN) return;
    int r = i / NN, n = i - r*NN;
    int off = g_bsum[r*SB + (n >> 10)];
    int v = g_rowptr[r*(NN+1) + n] + off;
    g_rowptr[r*(NN+1) + n] = v;
    g_cursor[r*NN + n] = v;
}

// fill CSR with packed (src, fp16 weight) entries
__global__ void fill_k(const int* __restrict__ edges) {
    int i = blockIdx.x * blockDim.x + threadIdx.x;
    if (i >= RR*EE) return;
    int r = i / EE, e = i - r*EE;
    int src = edges[(size_t)r*2*EE + e];
    int dst = edges[(size_t)r*2*EE + EE + e];
    float w = g_rno[r*NN + src];
    unsigned short hb = __half_as_ushort(__float2half_rn(w));  // sign bit = 0
    unsigned ent = ((unsigned)src << 15) | (unsigned)(hb & 0x7FFF);
    int pos = atomicAdd(&g_cursor[r*NN + dst], 1);
    g_pcsr[(size_t)r*EE + pos] = ent;
}

// ---------------- conversions ----------------
__global__ void conv_feat_k(const float* __restrict__ f) {
    int i = blockIdx.x * blockDim.x + threadIdx.x;
    if (i >= NN*DHH/2) return;
    float2 v = ((const float2*)f)[i];
    ((__half2*)g_f16)[i] = __floats2half2_rn(v.x, v.y);
}

// g_wt[l][col][pair] = half2(W_l[2p][col], W_l[2p+1][col])
__global__ void conv_w_k(const float* __restrict__ W0, const float* __restrict__ Wl) {
    int i = blockIdx.x * blockDim.x + threadIdx.x;
    if (i >= 3*DHH*256) return;
    int l = i / (DHH*256);
    int rem = i - l*DHH*256;
    int col = rem >> 8;
    int p = rem & 255;
    const float* src = (l == 0) ? W0 : Wl + (size_t)(l-1)*KK*DHH;
    __half2 hv = __floats2half2_rn(src[(size_t)(2*p)*DHH + col],
                                   src[(size_t)(2*p+1)*DHH + col]);
    g_wt[i] = *reinterpret_cast<unsigned*>(&hv);
}

// ---------------- aggregation: one warp per (r, dst); two edges in flight ----------------
// lanes 0-15 process even-offset edges, lanes 16-31 odd-offset edges, each lane
// loads 16B (8 halves) of the 256B row with LDG.128; final shfl(16) combine.
__global__ void __launch_bounds__(256) agg_k(int sel) {
    const __half* hin = (sel == 0) ? g_f16 : (sel == 1 ? g_h0h : g_h1h);
    int w = (blockIdx.x * blockDim.x + threadIdx.x) >> 5;
    if (w >= RR*NN) return;
    int lane = threadIdx.x & 31;
    int half = lane >> 4;          // which edge of the pair
    int hl   = lane & 15;          // 16B chunk within row
    int r = w / NN, n = w - r*NN;
    int e0 = g_rowptr[r*(NN+1) + n];
    int e1 = g_rowptr[r*(NN+1) + n + 1];
    const unsigned* pc = g_pcsr + (size_t)r*EE;

    float a0=0.f,a1=0.f,a2=0.f,a3=0.f,a4=0.f,a5=0.f,a6=0.f,a7=0.f;
    for (int e = e0 + half; e < e1; e += 2) {
        unsigned ent = __ldg(pc + e);
        int s = ent >> 15;
        float wgt = __half2float(__ushort_as_half((unsigned short)(ent & 0x7FFF)));
        uint4 v = __ldg((const uint4*)(hin + (size_t)s*DHH) + hl);
        float2 f0 = __half22float2(*reinterpret_cast<__half2*>(&v.x));
        float2 f1 = __half22float2(*reinterpret_cast<__half2*>(&v.y));
        float2 f2 = __half22float2(*reinterpret_cast<__half2*>(&v.z));
        float2 f3 = __half22float2(*reinterpret_cast<__half2*>(&v.w));
        a0 = fmaf(wgt, f0.x, a0); a1 = fmaf(wgt, f0.y, a1);
        a2 = fmaf(wgt, f1.x, a2); a3 = fmaf(wgt, f1.y, a3);
        a4 = fmaf(wgt, f2.x, a4); a5 = fmaf(wgt, f2.y, a5);
        a6 = fmaf(wgt, f3.x, a6); a7 = fmaf(wgt, f3.y, a7);
    }
    // combine the two halves (lane i += lane i+16, same columns)
    a0 += __shfl_down_sync(0xFFFFFFFFu, a0, 16);
    a1 += __shfl_down_sync(0xFFFFFFFFu, a1, 16);
    a2 += __shfl_down_sync(0xFFFFFFFFu, a2, 16);
    a3 += __shfl_down_sync(0xFFFFFFFFu, a3, 16);
    a4 += __shfl_down_sync(0xFFFFFFFFu, a4, 16);
    a5 += __shfl_down_sync(0xFFFFFFFFu, a5, 16);
    a6 += __shfl_down_sync(0xFFFFFFFFu, a6, 16);
    a7 += __shfl_down_sync(0xFFFFFFFFu, a7, 16);

    if (half == 0) {
        float ri = g_rni[r*NN + n];
        __half2 p0 = __floats2half2_rn(ri*a0, ri*a1);
        __half2 p1 = __floats2half2_rn(ri*a2, ri*a3);
        __half2 p2 = __floats2half2_rn(ri*a4, ri*a5);
        __half2 p3 = __floats2half2_rn(ri*a6, ri*a7);
        uint4 o;
        o.x = *reinterpret_cast<unsigned*>(&p0);
        o.y = *reinterpret_cast<unsigned*>(&p1);
        o.z = *reinterpret_cast<unsigned*>(&p2);
        o.w = *reinterpret_cast<unsigned*>(&p3);
        *((uint4*)(g_aggh + (size_t)n*KK + r*DHH) + hl) = o;
    }
}

// ---------------- fp16 tensor-core GEMM + bias + relu (R3-proven) ----------------
__device__ __forceinline__ void mma_f16(float* c, const unsigned* a, const unsigned* b) {
    asm volatile(
        "mma.sync.aligned.m16n8k16.row.col.f32.f16.f16.f32 "
        "{%0,%1,%2,%3}, {%4,%5,%6,%7}, {%8,%9}, {%0,%1,%2,%3};"
        : "+f"(c[0]), "+f"(c[1]), "+f"(c[2]), "+f"(c[3])
        : "r"(a[0]), "r"(a[1]), "r"(a[2]), "r"(a[3]), "r"(b[0]), "r"(b[1]));
}

// BM=128, BN=128, BK=16, 256 threads, 8 warps 2(m)x4(n), warp tile 64x32
__global__ void __launch_bounds__(256) gemm_tc_k(int layer, const float* __restrict__ Bv,
                                                 int outsel) {
    __shared__ unsigned As[2][128][12];
    __shared__ unsigned Bs[2][128][12];

    __half* O = (outsel == 0) ? g_h0h : g_h1h;
    const __half* A = g_aggh;
    const unsigned* Wt = g_wt + (size_t)layer*DHH*256;

    int tid = threadIdx.x;
    int rb = blockIdx.x * 128;
    int wid = tid >> 5, lane = tid & 31;
    int wm = wid & 1, wn = wid >> 1;
    int g = lane >> 2, t = lane & 3;

    uint2 areg[2], breg[2];
    float acc[4][4][4];
    #pragma unroll
    for (int mt = 0; mt < 4; mt++)
        #pragma unroll
        for (int nt = 0; nt < 4; nt++)
            #pragma unroll
            for (int j = 0; j < 4; j++) acc[mt][nt][j] = 0.f;

    auto loadg = [&](int kt) {
        int k0 = kt * 16;
        #pragma unroll
        for (int p = 0; p < 2; p++) {
            int idx = tid + p*256;
            int row = idx >> 2, q = idx & 3;
            int gr = rb + row;
            areg[p] = (gr < NN) ? *(const uint2*)(A + (size_t)gr*KK + k0 + q*4)
                                : make_uint2(0u, 0u);
            breg[p] = *(const uint2*)(Wt + (size_t)row*256 + kt*8 + q*2);
        }
    };
    auto stores = [&](int buf) {
        #pragma unroll
        for (int p = 0; p < 2; p++) {
            int idx = tid + p*256;
            int row = idx >> 2, q = idx & 3;
            As[buf][row][2*q]   = areg[p].x;
            As[buf][row][2*q+1] = areg[p].y;
            Bs[buf][row][2*q]   = breg[p].x;
            Bs[buf][row][2*q+1] = breg[p].y;
        }
    };

    loadg(0);
    stores(0);
    __syncthreads();

    for (int kt = 0; kt < 32; kt++) {
        int cur = kt & 1;
        if (kt < 31) loadg(kt + 1);

        unsigned af[4][4], bf[4][2];
        #pragma unroll
        for (int mt = 0; mt < 4; mt++) {
            int r0 = wm*64 + mt*16 + g;
            af[mt][0] = As[cur][r0    ][t];
            af[mt][1] = As[cur][r0 + 8][t];
            af[mt][2] = As[cur][r0    ][t + 4];
            af[mt][3] = As[cur][r0 + 8][t + 4];
        }
        #pragma unroll
        for (int nt = 0; nt < 4; nt++) {
            int c0 = wn*32 + nt*8 + g;
            bf[nt][0] = Bs[cur][c0][t];
            bf[nt][1] = Bs[cur][c0][t + 4];
        }
        #pragma unroll
        for (int mt = 0; mt < 4; mt++)
            #pragma unroll
            for (int nt = 0; nt < 4; nt++)
                mma_f16(acc[mt][nt], af[mt], bf[nt]);

        if (kt < 31) {
            __syncthreads();
            stores((kt + 1) & 1);
            __syncthreads();
        }
    }

    float bias[4][2];
    #pragma unroll
    for (int nt = 0; nt < 4; nt++) {
        int c0 = wn*32 + nt*8 + 2*t;
        #pragma unroll
        for (int j = 0; j < 2; j++) {
            float s = 0.f;
            #pragma unroll
            for (int r = 0; r < RR; r++) s += Bv[r*DHH + c0 + j];
            bias[nt][j] = s;
        }
    }
    #pragma unroll
    for (int mt = 0; mt < 4; mt++) {
        int r0 = rb + wm*64 + mt*16 + g;
        #pragma unroll
        for (int nt = 0; nt < 4; nt++) {
            int c = wn*32 + nt*8 + 2*t;
            if (r0 < NN) {
                *(__half2*)(O + (size_t)r0*DHH + c) =
                    __floats2half2_rn(fmaxf(acc[mt][nt][0] + bias[nt][0], 0.f),
                                      fmaxf(acc[mt][nt][1] + bias[nt][1], 0.f));
            }
            if (r0 + 8 < NN) {
                *(__half2*)(O + (size_t)(r0+8)*DHH + c) =
                    __floats2half2_rn(fmaxf(acc[mt][nt][2] + bias[nt][0], 0.f),
                                      fmaxf(acc[mt][nt][3] + bias[nt][1], 0.f));
            }
        }
    }
}

// ---------------- pooling + classifier ----------------
__global__ void bounds_k(const int* __restrict__ gid) {
    int i = blockIdx.x * blockDim.x + threadIdx.x;
    if (i > NN) return;
    int cur  = (i < NN) ? gid[i] : GG;
    int prev = (i == 0) ? -1     : gid[i-1];
    for (int g = prev + 1; g <= cur; g++) g_gstart[g] = i;
}

// 512 threads: 4 row-lanes x 128 cols, partial sums reduced through smem
__global__ void pool_k() {
    __shared__ float sh[3*DHH];
    int g = blockIdx.x;
    int j = threadIdx.x & 127;
    int rl = threadIdx.x >> 7;      // 0..3
    int a = g_gstart[g], b = g_gstart[g+1];
    float s = 0.f;
    for (int n = a + rl; n < b; n += 4)
        s += __half2float(g_h0h[(size_t)n*DHH + j]);
    if (rl > 0) sh[(rl-1)*DHH + j] = s;
    __syncthreads();
    if (rl == 0) {
        s += sh[j] + sh[DHH + j] + sh[2*DHH + j];
        float c = fmaxf((float)(b - a), 1.0f);
        g_hg[g*DHH + j] = s / c;
    }
}

__global__ void cls_k(const float* __restrict__ Wc, const float* __restrict__ bc,
                      float* __restrict__ out) {
    int idx = blockIdx.x * blockDim.x + threadIdx.x;
    if (idx >= GG*NCC) return;
    int g = idx / NCC, c = idx - g*NCC;
    float s = bc[c];
    #pragma unroll 8
    for (int k = 0; k < DHH; k++)
        s = fmaf(g_hg[g*DHH + k], Wc[k*NCC + c], s);
    out[idx] = s;
}

// ---------------- launch ----------------
extern "C" void kernel_launch(void* const* d_in, const int* in_sizes, int n_in,
                              void* d_out, int out_size) {
    const float* features = (const float*)d_in[0];
    const int*   edges    = (const int*)  d_in[1];
    const int*   gids     = (const int*)  d_in[2];
    const float* W0       = (const float*)d_in[3];
    const float* b0       = (const float*)d_in[4];
    const float* Wl       = (const float*)d_in[5];
    const float* bl       = (const float*)d_in[6];
    const float* Wc       = (const float*)d_in[7];
    const float* bc       = (const float*)d_in[8];
    float* out = (float*)d_out;

    zero_deg_k <<<(RR*NN + 255)/256, 256>>>();
    count_deg_k<<<(RR*EE + 255)/256, 256>>>(edges);
    rnorm_k    <<<(RR*NN + 255)/256, 256>>>();
    scan1_k    <<<dim3(SB, RR), 1024>>>();
    scan2_k    <<<1, RR>>>();
    scan3_k    <<<(RR*NN + 255)/256, 256>>>();
    fill_k     <<<(RR*EE + 255)/256, 256>>>(edges);
    conv_feat_k<<<(NN*DHH/2 + 255)/256, 256>>>(features);
    conv_w_k   <<<(3*DHH*256 + 255)/256, 256>>>(W0, Wl);

    const int AGG_BLOCKS  = (RR*NN*32 + 255)/256;
    const int GEMM_BLOCKS = (NN + 127)/128;

    agg_k    <<<AGG_BLOCKS, 256>>>(0);
    gemm_tc_k<<<GEMM_BLOCKS, 256>>>(0, b0, 0);
    agg_k    <<<AGG_BLOCKS, 256>>>(1);
    gemm_tc_k<<<GEMM_BLOCKS, 256>>>(1, bl, 1);
    agg_k    <<<AGG_BLOCKS, 256>>>(2);
    gemm_tc_k<<<GEMM_BLOCKS, 256>>>(2, bl + RR*DHH, 0);

    bounds_k<<<(NN + 256)/256, 256>>>(gids);
    pool_k  <<<GG, 512>>>();
    cls_k   <<<(GG*NCC + 255)/256, 256>>>(Wc, bc, out);
}